// round 17
// baseline (speedup 1.0000x reference)
#include <cuda_runtime.h>
#include <cuda_bf16.h>

// ChamferDistance: B=4, C=3, N=M=8192, fp32.
// dist(n,m) = 2*hx - 2*(x.y - hy);  min_m dist = 2*hx - 2*max_m(x.y - hy)
// R17 = R16 with the reduce kernel rebuilt for memory parallelism:
//   float4 loads (4 keys/thread), 128 blocks x 128 threads -> all SMs busy,
//   MLP=16 independent LDG.128 per thread. Main kernel byte-for-byte R16.

#define NPTS     8192
#define NBATCH   4
#define THREADS  128
#define QPT      4            // queries per thread -> 512 queries per block
#define QTILE    (THREADS * QPT)
#define TCHUNK   512          // targets per block
#define NQT      (NPTS / QTILE)    // 16 query tiles
#define NTC      (NPTS / TCHUNK)   // 16 target chunks
#define NUNITS   (2 * NBATCH * NQT * NTC)   // 2048
#define NQUERY   (2 * NBATCH * NPTS)        // 65536
#define RBLOCKS  128
#define RTHREADS 128

__device__ float g_part[NTC * NQUERY];   // [tc][key] partial (max t' - hx)
__device__ float g_bsum[RBLOCKS];
__device__ unsigned g_count;             // zero-init; last reduce block resets it

typedef unsigned long long u64;

__device__ __forceinline__ u64 fma2(u64 a, u64 b, u64 c) {
    u64 d;
    asm("fma.rn.f32x2 %0, %1, %2, %3;" : "=l"(d) : "l"(a), "l"(b), "l"(c));
    return d;
}
__device__ __forceinline__ u64 pack2(float x) {
    u64 d;
    asm("mov.b64 %0, {%1, %1};" : "=l"(d) : "f"(x));
    return d;
}
__device__ __forceinline__ void unpack2(u64 v, float& lo, float& hi) {
    asm("mov.b64 {%0, %1}, %2;" : "=f"(lo), "=f"(hi) : "l"(v));
}
__device__ __forceinline__ void lds_v2u64(unsigned addr, u64& a, u64& b) {
    asm volatile("ld.shared.v2.u64 {%0, %1}, [%2];" : "=l"(a), "=l"(b) : "r"(addr));
}

__global__ __launch_bounds__(THREADS)
void chamfer_main_kernel(const float* __restrict__ pred,
                         const float* __restrict__ targ) {
    const int u     = blockIdx.x;
    const int tc    = u & (NTC - 1);
    const int qt    = (u / NTC) & (NQT - 1);
    const int bd    = u / (NTC * NQT);
    const int b     = bd & (NBATCH - 1);
    const int dir   = bd >> 2;

    const float* __restrict__ X = dir ? targ : pred;
    const float* __restrict__ Y = dir ? pred : targ;
    const float* __restrict__ Xb = X + (size_t)b * 3 * NPTS;
    const float* __restrict__ Yb = Y + (size_t)b * 3 * NPTS;

    __shared__ float s_y0[TCHUNK], s_y1[TCHUNK], s_y2[TCHUNK], s_nh[TCHUNK];

    const int tid = threadIdx.x;

    // ---- stage target chunk into SoA smem: {y0, y1, y2, -0.5*||y||^2} ----
    const int tbase = tc * TCHUNK;
    #pragma unroll
    for (int i = tid; i < TCHUNK; i += THREADS) {
        float y0 = Yb[tbase + i];
        float y1 = Yb[NPTS + tbase + i];
        float y2 = Yb[2 * NPTS + tbase + i];
        s_y0[i] = y0;
        s_y1[i] = y1;
        s_y2[i] = y2;
        s_nh[i] = -0.5f * (y0 * y0 + y1 * y1 + y2 * y2);
    }

    // ---- query points (QPT per thread) in registers, packed broadcast ----
    const int qbase = qt * QTILE;
    u64 xp0[QPT], xp1[QPT], xp2[QPT];
    float hx[QPT];
    #pragma unroll
    for (int q = 0; q < QPT; q++) {
        int n = qbase + q * THREADS + tid;
        float x0 = Xb[n];
        float x1 = Xb[NPTS + n];
        float x2 = Xb[2 * NPTS + n];
        xp0[q] = pack2(x0);
        xp1[q] = pack2(x1);
        xp2[q] = pack2(x2);
        hx[q] = 0.5f * (x0 * x0 + x1 * x1 + x2 * x2);
    }
    __syncthreads();

    unsigned a0 = (unsigned)__cvta_generic_to_shared(s_y0);
    unsigned a1 = (unsigned)__cvta_generic_to_shared(s_y1);
    unsigned a2 = (unsigned)__cvta_generic_to_shared(s_y2);
    unsigned ah = (unsigned)__cvta_generic_to_shared(s_nh);

    float m0[QPT], m1[QPT];
    #pragma unroll
    for (int q = 0; q < QPT; q++) { m0[q] = -3.402823466e38f; m1[q] = m0[q]; }

    // ---- main loop: 4 targets per iteration, all uniform-address broadcast LDS ----
    #pragma unroll 2
    for (int j = 0; j < TCHUNK / 4; j++) {
        u64 A0, A1, B0, B1, C0, C1, H0, H1;
        unsigned off = j * 16;
        lds_v2u64(a0 + off, A0, A1);
        lds_v2u64(a1 + off, B0, B1);
        lds_v2u64(a2 + off, C0, C1);
        lds_v2u64(ah + off, H0, H1);

        #pragma unroll
        for (int q = 0; q < QPT; q++) {
            u64 t0 = fma2(xp0[q], A0, H0);
            u64 t1 = fma2(xp0[q], A1, H1);
            t0 = fma2(xp1[q], B0, t0);
            t1 = fma2(xp1[q], B1, t1);
            t0 = fma2(xp2[q], C0, t0);
            t1 = fma2(xp2[q], C1, t1);
            float l0, h0, l1, h1;
            unpack2(t0, l0, h0);
            unpack2(t1, l1, h1);
            m0[q] = fmaxf(m0[q], l0);
            m1[q] = fmaxf(m1[q], h0);
            m0[q] = fmaxf(m0[q], l1);
            m1[q] = fmaxf(m1[q], h1);
        }
    }

    // ---- epilogue: plain-store private partial (max t' - hx); no atomics ----
    const int key0 = bd * NPTS + qbase + tid;
    float* __restrict__ dst = &g_part[(size_t)tc * NQUERY + key0];
    #pragma unroll
    for (int q = 0; q < QPT; q++)
        dst[q * THREADS] = fmaxf(m0[q], m1[q]) - hx[q];
}

__global__ __launch_bounds__(RTHREADS)
void chamfer_reduce_kernel(float* __restrict__ out) {
    __shared__ float wsum[RTHREADS / 32];
    const int tid = threadIdx.x;
    // each thread folds 4 adjacent keys via float4 loads (16 independent LDG.128)
    const int key4 = blockIdx.x * RTHREADS + tid;   // 0 .. 16383

    const float4* __restrict__ p = (const float4*)g_part;
    float4 v = __ldcg(&p[key4]);
    #pragma unroll
    for (int t = 1; t < NTC; t++) {
        float4 w = __ldcg(&p[(size_t)t * (NQUERY / 4) + key4]);
        v.x = fmaxf(v.x, w.x);
        v.y = fmaxf(v.y, w.y);
        v.z = fmaxf(v.z, w.z);
        v.w = fmaxf(v.w, w.w);
    }
    float s = (v.x + v.y) + (v.z + v.w);

    // block sum
    #pragma unroll
    for (int off = 16; off > 0; off >>= 1)
        s += __shfl_xor_sync(0xffffffffu, s, off);
    if ((tid & 31) == 0) wsum[tid >> 5] = s;
    __syncthreads();
    if (tid == 0) {
        float bs = 0.0f;
        #pragma unroll
        for (int i = 0; i < RTHREADS / 32; i++) bs += wsum[i];
        g_bsum[blockIdx.x] = bs;
        __threadfence();
        unsigned c = atomicAdd(&g_count, 1u);
        if (c == RBLOCKS - 1) {
            float tot = 0.0f;
            #pragma unroll
            for (int i = 0; i < RBLOCKS; i++) tot += __ldcg(&g_bsum[i]);
            // min dist per query = -2 * t_full; two means each over B*NPTS
            out[0] = tot * (-2.0f / (float)(NBATCH * NPTS));
            g_count = 0u;   // self-reset for the next graph replay
        }
    }
}

extern "C" void kernel_launch(void* const* d_in, const int* in_sizes, int n_in,
                              void* d_out, int out_size) {
    const float* pred = (const float*)d_in[0];
    const float* targ = (const float*)d_in[1];
    float* out = (float*)d_out;

    chamfer_main_kernel<<<NUNITS, THREADS>>>(pred, targ);
    chamfer_reduce_kernel<<<RBLOCKS, RTHREADS>>>(out);
}